// round 8
// baseline (speedup 1.0000x reference)
#include <cuda_runtime.h>
#include <cuda_bf16.h>

// Problem constants (fixed by the dataset)
#define NN   50000
#define EE   600000
#define HH   128
#define EDD  16
#define BB   256
#define LL   5

#define TILE_M    64
#define AS_STRIDE 132   // padded row stride for A tile (floats)
#define SMEM_BYTES ((TILE_M*AS_STRIDE + HH*HH) * 4)

// ---------------- persistent device scratch ----------------
__device__ float g_h[(size_t)NN * HH];
__device__ float g_agg[(size_t)NN * HH];
__device__ float g_x[(size_t)NN * HH];
__device__ float g_vn[BB * HH];
__device__ float g_pooled[BB * HH];
__device__ int   g_off[BB + 1];

// ---------------- f32x2 helpers (Blackwell packed fp32 pipe) ----------------
__device__ __forceinline__ unsigned long long pack2(float a) {
    unsigned long long r;
    asm("mov.b64 %0, {%1, %1};" : "=l"(r) : "f"(a));
    return r;
}
__device__ __forceinline__ void fma2(unsigned long long& d,
                                     unsigned long long a,
                                     unsigned long long b) {
    asm("fma.rn.f32x2 %0, %1, %2, %0;" : "+l"(d) : "l"(a), "l"(b));
}

// ---------------- smem staging ----------------
__device__ __forceinline__ void load_W(float* Ws, const float* __restrict__ W, int tid) {
    const float4* W4 = (const float4*)W;
    float4* S4 = (float4*)Ws;
#pragma unroll
    for (int i = 0; i < 32; i++) S4[i * 128 + tid] = W4[i * 128 + tid];
}

__device__ __forceinline__ void load_A(float* As, const float* __restrict__ X,
                                       int row0, int tid, int nrows) {
#pragma unroll
    for (int it = 0; it < 16; it++) {
        int idx = it * 128 + tid;       // 0..2047 float4 slots
        int r   = idx >> 5;             // 32 float4 per 128-float row
        int cv  = idx & 31;
        float4 v = make_float4(0.f, 0.f, 0.f, 0.f);
        if (row0 + r < nrows)
            v = *(const float4*)(X + (size_t)(row0 + r) * HH + cv * 4);
        *(float4*)(As + r * AS_STRIDE + cv * 4) = v;
    }
}

// 64x128 tile GEMM over K=128, 8x8 per-thread register blocking, f32x2 FMAs.
__device__ __forceinline__ void gemm_tile(const float* As, const float* Ws,
                                          unsigned long long acc[8][4],
                                          int ty, int tx) {
#pragma unroll 4
    for (int k = 0; k < HH; k++) {
        ulonglong2 b0 = *(const ulonglong2*)(Ws + k * HH + tx * 8);
        ulonglong2 b1 = *(const ulonglong2*)(Ws + k * HH + tx * 8 + 4);
#pragma unroll
        for (int i = 0; i < 8; i++) {
            unsigned long long a2 = pack2(As[(ty + i * 8) * AS_STRIDE + k]);
            fma2(acc[i][0], a2, b0.x);
            fma2(acc[i][1], a2, b0.y);
            fma2(acc[i][2], a2, b1.x);
            fma2(acc[i][3], a2, b1.y);
        }
    }
}

__device__ __forceinline__ void zero_acc(unsigned long long acc[8][4]) {
#pragma unroll
    for (int i = 0; i < 8; i++)
#pragma unroll
        for (int j = 0; j < 4; j++) acc[i][j] = 0ull;
}

// ---------------- kernels ----------------

// per-graph row offsets via binary search (batch is sorted)
extern "C" __global__ void k_offsets(const int* __restrict__ batch) {
    int b = threadIdx.x;  // 0..255
    int lo = 0, hi = NN;
    while (lo < hi) {
        int m = (lo + hi) >> 1;
        if (batch[m] < b) lo = m + 1; else hi = m;
    }
    g_off[b] = lo;
    if (b == 0) g_off[BB] = NN;
}

extern "C" __global__ void k_vninit(const float* __restrict__ vn_init) {
    g_vn[blockIdx.x * HH + threadIdx.x] = vn_init[threadIdx.x];
}

// h = X @ nW + nb + vn[batch];  also zeroes agg for this layer's scatter
extern "C" __global__ void __launch_bounds__(128)
k_node_encode(const float* __restrict__ xin, int first,
              const float* __restrict__ W, const float* __restrict__ bvec,
              const int* __restrict__ batch) {
    extern __shared__ float sm[];
    float* As = sm;
    float* Ws = sm + TILE_M * AS_STRIDE;
    int tid = threadIdx.x;
    const float* X = first ? xin : g_x;
    int row0 = blockIdx.x * TILE_M;

    load_W(Ws, W, tid);
    load_A(As, X, row0, tid, NN);
    __syncthreads();

    unsigned long long acc[8][4];
    zero_acc(acc);
    int ty = tid >> 4, tx = tid & 15;
    gemm_tile(As, Ws, acc, ty, tx);

    int c0 = tx * 8;
    float bb[8];
#pragma unroll
    for (int j = 0; j < 8; j++) bb[j] = bvec[c0 + j];

#pragma unroll
    for (int i = 0; i < 8; i++) {
        int gr = row0 + ty + i * 8;
        if (gr < NN) {
            int bg = batch[gr];
            const float* vrow = g_vn + bg * HH + c0;
            float2 p0 = *(float2*)&acc[i][0];
            float2 p1 = *(float2*)&acc[i][1];
            float2 p2 = *(float2*)&acc[i][2];
            float2 p3 = *(float2*)&acc[i][3];
            float4 o0, o1;
            o0.x = p0.x + bb[0] + vrow[0];
            o0.y = p0.y + bb[1] + vrow[1];
            o0.z = p1.x + bb[2] + vrow[2];
            o0.w = p1.y + bb[3] + vrow[3];
            o1.x = p2.x + bb[4] + vrow[4];
            o1.y = p2.y + bb[5] + vrow[5];
            o1.z = p3.x + bb[6] + vrow[6];
            o1.w = p3.y + bb[7] + vrow[7];
            *(float4*)(g_h + (size_t)gr * HH + c0)     = o0;
            *(float4*)(g_h + (size_t)gr * HH + c0 + 4) = o1;
            *(float4*)(g_agg + (size_t)gr * HH + c0)     = make_float4(0, 0, 0, 0);
            *(float4*)(g_agg + (size_t)gr * HH + c0 + 4) = make_float4(0, 0, 0, 0);
        }
    }
}

// fused edge path: ea = attr @ eW + eb; msg = h[src] + ea; agg[dst] += msg
#define EDGE_BLOCKS 18750
extern "C" __global__ void __launch_bounds__(256)
k_edge(const float* __restrict__ edge_attr, const float* __restrict__ eW,
       const float* __restrict__ eb, const int* __restrict__ ei) {
    __shared__ float Ws[EDD * HH];   // 8 KB
    __shared__ float bs[HH];
    int tid = threadIdx.x;
    for (int i = tid; i < (EDD * HH) / 4; i += 256)
        ((float4*)Ws)[i] = ((const float4*)eW)[i];
    if (tid < HH) bs[tid] = eb[tid];
    __syncthreads();

    int warp = tid >> 5, lane = tid & 31;
    int warps_total = EDGE_BLOCKS * 8;
    for (int e = blockIdx.x * 8 + warp; e < EE; e += warps_total) {
        int src = ei[e];
        int dst = ei[EE + e];
        float a = (lane < EDD) ? edge_attr[(size_t)e * EDD + lane] : 0.f;
        float4 acc = *(const float4*)&bs[lane * 4];
#pragma unroll
        for (int k = 0; k < EDD; k++) {
            float ak = __shfl_sync(0xffffffffu, a, k);
            float4 w = *(const float4*)&Ws[k * HH + lane * 4];
            acc.x += ak * w.x;
            acc.y += ak * w.y;
            acc.z += ak * w.z;
            acc.w += ak * w.w;
        }
        float4 hv = *(const float4*)(g_h + (size_t)src * HH + lane * 4);
        acc.x += hv.x; acc.y += hv.y; acc.z += hv.z; acc.w += hv.w;
        float* p = g_agg + (size_t)dst * HH + lane * 4;
        asm volatile("red.global.add.v4.f32 [%0], {%1, %2, %3, %4};"
                     :: "l"(p), "f"(acc.x), "f"(acc.y), "f"(acc.z), "f"(acc.w)
                     : "memory");
    }
}

// xn = relu( relu(agg @ W1 + b1) @ W2 + b2 )  — both GEMMs fused, T stays in smem
extern "C" __global__ void __launch_bounds__(128)
k_mlp(const float* __restrict__ W1, const float* __restrict__ b1,
      const float* __restrict__ W2, const float* __restrict__ b2) {
    extern __shared__ float sm[];
    float* As = sm;
    float* Ws = sm + TILE_M * AS_STRIDE;
    int tid = threadIdx.x;
    int ty = tid >> 4, tx = tid & 15, c0 = tx * 8;
    int row0 = blockIdx.x * TILE_M;

    load_W(Ws, W1, tid);
    load_A(As, g_agg, row0, tid, NN);
    __syncthreads();

    unsigned long long acc[8][4];
    zero_acc(acc);
    gemm_tile(As, Ws, acc, ty, tx);
    __syncthreads();  // all threads done reading As/Ws

    // T = relu(acc + b1)  -> back into As; load W2
    float bb1[8];
#pragma unroll
    for (int j = 0; j < 8; j++) bb1[j] = b1[c0 + j];
#pragma unroll
    for (int i = 0; i < 8; i++) {
        float* dst = As + (ty + i * 8) * AS_STRIDE + c0;
        float2 p0 = *(float2*)&acc[i][0];
        float2 p1 = *(float2*)&acc[i][1];
        float2 p2 = *(float2*)&acc[i][2];
        float2 p3 = *(float2*)&acc[i][3];
        dst[0] = fmaxf(p0.x + bb1[0], 0.f);
        dst[1] = fmaxf(p0.y + bb1[1], 0.f);
        dst[2] = fmaxf(p1.x + bb1[2], 0.f);
        dst[3] = fmaxf(p1.y + bb1[3], 0.f);
        dst[4] = fmaxf(p2.x + bb1[4], 0.f);
        dst[5] = fmaxf(p2.y + bb1[5], 0.f);
        dst[6] = fmaxf(p3.x + bb1[6], 0.f);
        dst[7] = fmaxf(p3.y + bb1[7], 0.f);
    }
    load_W(Ws, W2, tid);
    __syncthreads();

    zero_acc(acc);
    gemm_tile(As, Ws, acc, ty, tx);

    float bb2[8];
#pragma unroll
    for (int j = 0; j < 8; j++) bb2[j] = b2[c0 + j];
#pragma unroll
    for (int i = 0; i < 8; i++) {
        int gr = row0 + ty + i * 8;
        if (gr < NN) {
            float2 p0 = *(float2*)&acc[i][0];
            float2 p1 = *(float2*)&acc[i][1];
            float2 p2 = *(float2*)&acc[i][2];
            float2 p3 = *(float2*)&acc[i][3];
            float4 o0, o1;
            o0.x = fmaxf(p0.x + bb2[0], 0.f);
            o0.y = fmaxf(p0.y + bb2[1], 0.f);
            o0.z = fmaxf(p1.x + bb2[2], 0.f);
            o0.w = fmaxf(p1.y + bb2[3], 0.f);
            o1.x = fmaxf(p2.x + bb2[4], 0.f);
            o1.y = fmaxf(p2.y + bb2[5], 0.f);
            o1.z = fmaxf(p3.x + bb2[6], 0.f);
            o1.w = fmaxf(p3.y + bb2[7], 0.f);
            *(float4*)(g_x + (size_t)gr * HH + c0)     = o0;
            *(float4*)(g_x + (size_t)gr * HH + c0 + 4) = o1;
        }
    }
}

// pooled[b] = mean over contiguous rows of g_x (batch is sorted)
extern "C" __global__ void k_pool() {
    int b = blockIdx.x, j = threadIdx.x;
    int s = g_off[b], e2 = g_off[b + 1];
    float a0 = 0, a1 = 0, a2 = 0, a3 = 0;
    int r = s;
    for (; r + 4 <= e2; r += 4) {
        a0 += g_x[(size_t)(r + 0) * HH + j];
        a1 += g_x[(size_t)(r + 1) * HH + j];
        a2 += g_x[(size_t)(r + 2) * HH + j];
        a3 += g_x[(size_t)(r + 3) * HH + j];
    }
    for (; r < e2; r++) a0 += g_x[(size_t)r * HH + j];
    float cnt = (float)(e2 - s);
    if (cnt < 1.f) cnt = 1.f;
    g_pooled[b * HH + j] = (a0 + a1 + a2 + a3) / cnt;
}

// vn += relu( relu(pooled @ w0 + b0) @ w1 + b1 )
extern "C" __global__ void k_vn(const float* __restrict__ w0, const float* __restrict__ b0,
                                const float* __restrict__ w1, const float* __restrict__ b1) {
    __shared__ float p[HH];
    __shared__ float t[HH];
    int b = blockIdx.x, j = threadIdx.x;
    p[j] = g_pooled[b * HH + j];
    __syncthreads();
    float s = b0[j];
#pragma unroll 4
    for (int k = 0; k < HH; k++) s += p[k] * w0[k * HH + j];
    t[j] = fmaxf(s, 0.f);
    __syncthreads();
    float s2 = b1[j];
#pragma unroll 4
    for (int k = 0; k < HH; k++) s2 += t[k] * w1[k * HH + j];
    g_vn[b * HH + j] += fmaxf(s2, 0.f);
}

// out = pooled @ fc_W + fc_b
extern "C" __global__ void k_fc(const float* __restrict__ W, const float* __restrict__ bias,
                                float* __restrict__ out) {
    __shared__ float p[HH];
    int b = blockIdx.x, j = threadIdx.x;
    p[j] = g_pooled[b * HH + j];
    __syncthreads();
    float s = bias[j];
#pragma unroll 4
    for (int k = 0; k < HH; k++) s += p[k] * W[k * HH + j];
    out[b * HH + j] = s;
}

// ---------------- launch ----------------
extern "C" void kernel_launch(void* const* d_in, const int* in_sizes, int n_in,
                              void* d_out, int out_size) {
    const float* x         = (const float*)d_in[0];
    const float* edge_attr = (const float*)d_in[1];
    const float* node_W    = (const float*)d_in[2];
    const float* node_b    = (const float*)d_in[3];
    const float* edge_W    = (const float*)d_in[4];
    const float* edge_b    = (const float*)d_in[5];
    const float* mlp1_W    = (const float*)d_in[6];
    const float* mlp1_b    = (const float*)d_in[7];
    const float* mlp2_W    = (const float*)d_in[8];
    const float* mlp2_b    = (const float*)d_in[9];
    const float* vn_w0     = (const float*)d_in[10];
    const float* vn_b0     = (const float*)d_in[11];
    const float* vn_w1     = (const float*)d_in[12];
    const float* vn_b1     = (const float*)d_in[13];
    const float* fc_W      = (const float*)d_in[14];
    const float* fc_b      = (const float*)d_in[15];
    const float* vn_init   = (const float*)d_in[16];
    const int*   edge_idx  = (const int*)d_in[17];
    const int*   batch     = (const int*)d_in[18];

    cudaFuncSetAttribute(k_node_encode, cudaFuncAttributeMaxDynamicSharedMemorySize, SMEM_BYTES);
    cudaFuncSetAttribute(k_mlp,         cudaFuncAttributeMaxDynamicSharedMemorySize, SMEM_BYTES);

    int gM = (NN + TILE_M - 1) / TILE_M;  // 782

    k_offsets<<<1, BB>>>(batch);
    k_vninit<<<BB, HH>>>(vn_init);

    for (int l = 0; l < LL; l++) {
        k_node_encode<<<gM, 128, SMEM_BYTES>>>(
            x, (l == 0) ? 1 : 0,
            node_W + (size_t)l * HH * HH, node_b + (size_t)l * HH, batch);
        k_edge<<<EDGE_BLOCKS, 256>>>(
            edge_attr, edge_W + (size_t)l * EDD * HH, edge_b + (size_t)l * HH, edge_idx);
        k_mlp<<<gM, 128, SMEM_BYTES>>>(
            mlp1_W + (size_t)l * HH * HH, mlp1_b + (size_t)l * HH,
            mlp2_W + (size_t)l * HH * HH, mlp2_b + (size_t)l * HH);
        k_pool<<<BB, HH>>>();
        if (l + 1 < LL) k_vn<<<BB, HH>>>(vn_w0, vn_b0, vn_w1, vn_b1);
    }
    k_fc<<<BB, HH>>>(fc_W, fc_b, (float*)d_out);
}

// round 9
// speedup vs baseline: 1.0029x; 1.0029x over previous
#include <cuda_runtime.h>
#include <cuda_bf16.h>

// Problem constants (fixed by the dataset)
#define NN   50000
#define EE   600000
#define HH   128
#define EDD  16
#define BB   256
#define LL   5

#define TILE_M    64
#define AS_STRIDE 132   // padded row stride for A tile (floats)
#define SMEM_BYTES ((TILE_M*AS_STRIDE + HH*HH) * 4)

// ---------------- persistent device scratch ----------------
__device__ float g_h[(size_t)NN * HH];
__device__ float g_agg[(size_t)NN * HH];
__device__ float g_x[(size_t)NN * HH];
__device__ float g_vn[BB * HH];
__device__ float g_pooled[BB * HH];
__device__ int   g_off[BB + 1];

// ---------------- f32x2 helpers (Blackwell packed fp32 pipe) ----------------
__device__ __forceinline__ unsigned long long pack2(float a) {
    unsigned long long r;
    asm("mov.b64 %0, {%1, %1};" : "=l"(r) : "f"(a));
    return r;
}
__device__ __forceinline__ void fma2(unsigned long long& d,
                                     unsigned long long a,
                                     unsigned long long b) {
    asm("fma.rn.f32x2 %0, %1, %2, %0;" : "+l"(d) : "l"(a), "l"(b));
}

// ---------------- smem staging ----------------
__device__ __forceinline__ void load_W(float* Ws, const float* __restrict__ W, int tid) {
    const float4* W4 = (const float4*)W;
    float4* S4 = (float4*)Ws;
#pragma unroll
    for (int i = 0; i < 32; i++) S4[i * 128 + tid] = W4[i * 128 + tid];
}

__device__ __forceinline__ void load_A(float* As, const float* __restrict__ X,
                                       int row0, int tid, int nrows) {
#pragma unroll
    for (int it = 0; it < 16; it++) {
        int idx = it * 128 + tid;       // 0..2047 float4 slots
        int r   = idx >> 5;             // 32 float4 per 128-float row
        int cv  = idx & 31;
        float4 v = make_float4(0.f, 0.f, 0.f, 0.f);
        if (row0 + r < nrows)
            v = *(const float4*)(X + (size_t)(row0 + r) * HH + cv * 4);
        *(float4*)(As + r * AS_STRIDE + cv * 4) = v;
    }
}

// 64x128 tile GEMM over K=128, 8x8 per-thread register blocking, f32x2 FMAs.
__device__ __forceinline__ void gemm_tile(const float* As, const float* Ws,
                                          unsigned long long acc[8][4],
                                          int ty, int tx) {
#pragma unroll 4
    for (int k = 0; k < HH; k++) {
        ulonglong2 b0 = *(const ulonglong2*)(Ws + k * HH + tx * 8);
        ulonglong2 b1 = *(const ulonglong2*)(Ws + k * HH + tx * 8 + 4);
#pragma unroll
        for (int i = 0; i < 8; i++) {
            unsigned long long a2 = pack2(As[(ty + i * 8) * AS_STRIDE + k]);
            fma2(acc[i][0], a2, b0.x);
            fma2(acc[i][1], a2, b0.y);
            fma2(acc[i][2], a2, b1.x);
            fma2(acc[i][3], a2, b1.y);
        }
    }
}

__device__ __forceinline__ void zero_acc(unsigned long long acc[8][4]) {
#pragma unroll
    for (int i = 0; i < 8; i++)
#pragma unroll
        for (int j = 0; j < 4; j++) acc[i][j] = 0ull;
}

// ---------------- kernels ----------------

// per-graph row offsets via binary search (batch is sorted)
extern "C" __global__ void k_offsets(const int* __restrict__ batch) {
    int b = threadIdx.x;  // 0..255
    int lo = 0, hi = NN;
    while (lo < hi) {
        int m = (lo + hi) >> 1;
        if (batch[m] < b) lo = m + 1; else hi = m;
    }
    g_off[b] = lo;
    if (b == 0) g_off[BB] = NN;
}

extern "C" __global__ void k_vninit(const float* __restrict__ vn_init) {
    g_vn[blockIdx.x * HH + threadIdx.x] = vn_init[threadIdx.x];
}

// h = X @ nW + nb + vn[batch];  also zeroes agg for this layer's scatter
extern "C" __global__ void __launch_bounds__(128)
k_node_encode(const float* __restrict__ xin, int first,
              const float* __restrict__ W, const float* __restrict__ bvec,
              const int* __restrict__ batch) {
    extern __shared__ float sm[];
    float* As = sm;
    float* Ws = sm + TILE_M * AS_STRIDE;
    int tid = threadIdx.x;
    const float* X = first ? xin : g_x;
    int row0 = blockIdx.x * TILE_M;

    load_W(Ws, W, tid);
    load_A(As, X, row0, tid, NN);
    __syncthreads();

    unsigned long long acc[8][4];
    zero_acc(acc);
    int ty = tid >> 4, tx = tid & 15;
    gemm_tile(As, Ws, acc, ty, tx);

    int c0 = tx * 8;
    float bb[8];
#pragma unroll
    for (int j = 0; j < 8; j++) bb[j] = bvec[c0 + j];

#pragma unroll
    for (int i = 0; i < 8; i++) {
        int gr = row0 + ty + i * 8;
        if (gr < NN) {
            int bg = batch[gr];
            const float* vrow = g_vn + bg * HH + c0;
            float2 p0 = *(float2*)&acc[i][0];
            float2 p1 = *(float2*)&acc[i][1];
            float2 p2 = *(float2*)&acc[i][2];
            float2 p3 = *(float2*)&acc[i][3];
            float4 o0, o1;
            o0.x = p0.x + bb[0] + vrow[0];
            o0.y = p0.y + bb[1] + vrow[1];
            o0.z = p1.x + bb[2] + vrow[2];
            o0.w = p1.y + bb[3] + vrow[3];
            o1.x = p2.x + bb[4] + vrow[4];
            o1.y = p2.y + bb[5] + vrow[5];
            o1.z = p3.x + bb[6] + vrow[6];
            o1.w = p3.y + bb[7] + vrow[7];
            *(float4*)(g_h + (size_t)gr * HH + c0)     = o0;
            *(float4*)(g_h + (size_t)gr * HH + c0 + 4) = o1;
            *(float4*)(g_agg + (size_t)gr * HH + c0)     = make_float4(0, 0, 0, 0);
            *(float4*)(g_agg + (size_t)gr * HH + c0 + 4) = make_float4(0, 0, 0, 0);
        }
    }
}

// fused edge path: ea = attr @ eW + eb; msg = h[src] + ea; agg[dst] += msg
#define EDGE_BLOCKS 18750
extern "C" __global__ void __launch_bounds__(256)
k_edge(const float* __restrict__ edge_attr, const float* __restrict__ eW,
       const float* __restrict__ eb, const int* __restrict__ ei) {
    __shared__ float Ws[EDD * HH];   // 8 KB
    __shared__ float bs[HH];
    int tid = threadIdx.x;
    for (int i = tid; i < (EDD * HH) / 4; i += 256)
        ((float4*)Ws)[i] = ((const float4*)eW)[i];
    if (tid < HH) bs[tid] = eb[tid];
    __syncthreads();

    int warp = tid >> 5, lane = tid & 31;
    int warps_total = EDGE_BLOCKS * 8;
    for (int e = blockIdx.x * 8 + warp; e < EE; e += warps_total) {
        int src = ei[e];
        int dst = ei[EE + e];
        float a = (lane < EDD) ? edge_attr[(size_t)e * EDD + lane] : 0.f;
        float4 acc = *(const float4*)&bs[lane * 4];
#pragma unroll
        for (int k = 0; k < EDD; k++) {
            float ak = __shfl_sync(0xffffffffu, a, k);
            float4 w = *(const float4*)&Ws[k * HH + lane * 4];
            acc.x += ak * w.x;
            acc.y += ak * w.y;
            acc.z += ak * w.z;
            acc.w += ak * w.w;
        }
        float4 hv = *(const float4*)(g_h + (size_t)src * HH + lane * 4);
        acc.x += hv.x; acc.y += hv.y; acc.z += hv.z; acc.w += hv.w;
        float* p = g_agg + (size_t)dst * HH + lane * 4;
        asm volatile("red.global.add.v4.f32 [%0], {%1, %2, %3, %4};"
                     :: "l"(p), "f"(acc.x), "f"(acc.y), "f"(acc.z), "f"(acc.w)
                     : "memory");
    }
}

// xn = relu( relu(agg @ W1 + b1) @ W2 + b2 )  — both GEMMs fused, T stays in smem
extern "C" __global__ void __launch_bounds__(128)
k_mlp(const float* __restrict__ W1, const float* __restrict__ b1,
      const float* __restrict__ W2, const float* __restrict__ b2) {
    extern __shared__ float sm[];
    float* As = sm;
    float* Ws = sm + TILE_M * AS_STRIDE;
    int tid = threadIdx.x;
    int ty = tid >> 4, tx = tid & 15, c0 = tx * 8;
    int row0 = blockIdx.x * TILE_M;

    load_W(Ws, W1, tid);
    load_A(As, g_agg, row0, tid, NN);
    __syncthreads();

    unsigned long long acc[8][4];
    zero_acc(acc);
    gemm_tile(As, Ws, acc, ty, tx);
    __syncthreads();  // all threads done reading As/Ws

    // T = relu(acc + b1)  -> back into As; load W2
    float bb1[8];
#pragma unroll
    for (int j = 0; j < 8; j++) bb1[j] = b1[c0 + j];
#pragma unroll
    for (int i = 0; i < 8; i++) {
        float* dst = As + (ty + i * 8) * AS_STRIDE + c0;
        float2 p0 = *(float2*)&acc[i][0];
        float2 p1 = *(float2*)&acc[i][1];
        float2 p2 = *(float2*)&acc[i][2];
        float2 p3 = *(float2*)&acc[i][3];
        dst[0] = fmaxf(p0.x + bb1[0], 0.f);
        dst[1] = fmaxf(p0.y + bb1[1], 0.f);
        dst[2] = fmaxf(p1.x + bb1[2], 0.f);
        dst[3] = fmaxf(p1.y + bb1[3], 0.f);
        dst[4] = fmaxf(p2.x + bb1[4], 0.f);
        dst[5] = fmaxf(p2.y + bb1[5], 0.f);
        dst[6] = fmaxf(p3.x + bb1[6], 0.f);
        dst[7] = fmaxf(p3.y + bb1[7], 0.f);
    }
    load_W(Ws, W2, tid);
    __syncthreads();

    zero_acc(acc);
    gemm_tile(As, Ws, acc, ty, tx);

    float bb2[8];
#pragma unroll
    for (int j = 0; j < 8; j++) bb2[j] = b2[c0 + j];
#pragma unroll
    for (int i = 0; i < 8; i++) {
        int gr = row0 + ty + i * 8;
        if (gr < NN) {
            float2 p0 = *(float2*)&acc[i][0];
            float2 p1 = *(float2*)&acc[i][1];
            float2 p2 = *(float2*)&acc[i][2];
            float2 p3 = *(float2*)&acc[i][3];
            float4 o0, o1;
            o0.x = fmaxf(p0.x + bb2[0], 0.f);
            o0.y = fmaxf(p0.y + bb2[1], 0.f);
            o0.z = fmaxf(p1.x + bb2[2], 0.f);
            o0.w = fmaxf(p1.y + bb2[3], 0.f);
            o1.x = fmaxf(p2.x + bb2[4], 0.f);
            o1.y = fmaxf(p2.y + bb2[5], 0.f);
            o1.z = fmaxf(p3.x + bb2[6], 0.f);
            o1.w = fmaxf(p3.y + bb2[7], 0.f);
            *(float4*)(g_x + (size_t)gr * HH + c0)     = o0;
            *(float4*)(g_x + (size_t)gr * HH + c0 + 4) = o1;
        }
    }
}

// pooled[b] = mean over contiguous rows of g_x (batch is sorted)
extern "C" __global__ void k_pool() {
    int b = blockIdx.x, j = threadIdx.x;
    int s = g_off[b], e2 = g_off[b + 1];
    float a0 = 0, a1 = 0, a2 = 0, a3 = 0;
    int r = s;
    for (; r + 4 <= e2; r += 4) {
        a0 += g_x[(size_t)(r + 0) * HH + j];
        a1 += g_x[(size_t)(r + 1) * HH + j];
        a2 += g_x[(size_t)(r + 2) * HH + j];
        a3 += g_x[(size_t)(r + 3) * HH + j];
    }
    for (; r < e2; r++) a0 += g_x[(size_t)r * HH + j];
    float cnt = (float)(e2 - s);
    if (cnt < 1.f) cnt = 1.f;
    g_pooled[b * HH + j] = (a0 + a1 + a2 + a3) / cnt;
}

// vn += relu( relu(pooled @ w0 + b0) @ w1 + b1 )
extern "C" __global__ void k_vn(const float* __restrict__ w0, const float* __restrict__ b0,
                                const float* __restrict__ w1, const float* __restrict__ b1) {
    __shared__ float p[HH];
    __shared__ float t[HH];
    int b = blockIdx.x, j = threadIdx.x;
    p[j] = g_pooled[b * HH + j];
    __syncthreads();
    float s = b0[j];
#pragma unroll 4
    for (int k = 0; k < HH; k++) s += p[k] * w0[k * HH + j];
    t[j] = fmaxf(s, 0.f);
    __syncthreads();
    float s2 = b1[j];
#pragma unroll 4
    for (int k = 0; k < HH; k++) s2 += t[k] * w1[k * HH + j];
    g_vn[b * HH + j] += fmaxf(s2, 0.f);
}

// out = pooled @ fc_W + fc_b
extern "C" __global__ void k_fc(const float* __restrict__ W, const float* __restrict__ bias,
                                float* __restrict__ out) {
    __shared__ float p[HH];
    int b = blockIdx.x, j = threadIdx.x;
    p[j] = g_pooled[b * HH + j];
    __syncthreads();
    float s = bias[j];
#pragma unroll 4
    for (int k = 0; k < HH; k++) s += p[k] * W[k * HH + j];
    out[b * HH + j] = s;
}

// ---------------- launch ----------------
extern "C" void kernel_launch(void* const* d_in, const int* in_sizes, int n_in,
                              void* d_out, int out_size) {
    const float* x         = (const float*)d_in[0];
    const float* edge_attr = (const float*)d_in[1];
    const float* node_W    = (const float*)d_in[2];
    const float* node_b    = (const float*)d_in[3];
    const float* edge_W    = (const float*)d_in[4];
    const float* edge_b    = (const float*)d_in[5];
    const float* mlp1_W    = (const float*)d_in[6];
    const float* mlp1_b    = (const float*)d_in[7];
    const float* mlp2_W    = (const float*)d_in[8];
    const float* mlp2_b    = (const float*)d_in[9];
    const float* vn_w0     = (const float*)d_in[10];
    const float* vn_b0     = (const float*)d_in[11];
    const float* vn_w1     = (const float*)d_in[12];
    const float* vn_b1     = (const float*)d_in[13];
    const float* fc_W      = (const float*)d_in[14];
    const float* fc_b      = (const float*)d_in[15];
    const float* vn_init   = (const float*)d_in[16];
    const int*   edge_idx  = (const int*)d_in[17];
    const int*   batch     = (const int*)d_in[18];

    cudaFuncSetAttribute(k_node_encode, cudaFuncAttributeMaxDynamicSharedMemorySize, SMEM_BYTES);
    cudaFuncSetAttribute(k_mlp,         cudaFuncAttributeMaxDynamicSharedMemorySize, SMEM_BYTES);

    int gM = (NN + TILE_M - 1) / TILE_M;  // 782

    k_offsets<<<1, BB>>>(batch);
    k_vninit<<<BB, HH>>>(vn_init);

    for (int l = 0; l < LL; l++) {
        k_node_encode<<<gM, 128, SMEM_BYTES>>>(
            x, (l == 0) ? 1 : 0,
            node_W + (size_t)l * HH * HH, node_b + (size_t)l * HH, batch);
        k_edge<<<EDGE_BLOCKS, 256>>>(
            edge_attr, edge_W + (size_t)l * EDD * HH, edge_b + (size_t)l * HH, edge_idx);
        k_mlp<<<gM, 128, SMEM_BYTES>>>(
            mlp1_W + (size_t)l * HH * HH, mlp1_b + (size_t)l * HH,
            mlp2_W + (size_t)l * HH * HH, mlp2_b + (size_t)l * HH);
        k_pool<<<BB, HH>>>();
        if (l + 1 < LL) k_vn<<<BB, HH>>>(vn_w0, vn_b0, vn_w1, vn_b1);
    }
    k_fc<<<BB, HH>>>(fc_W, fc_b, (float*)d_out);
}